// round 2
// baseline (speedup 1.0000x reference)
#include <cuda_runtime.h>
#include <cuda_fp16.h>
#include <cstdint>

// GINConv: out = SegmentSum_{CSR}(X[col]) @ W     (N=100000, DEG=16, D=128)
// Plan:
//   K1: convert X fp32 -> fp16 scratch (halves the L2 gather traffic)
//   K2: fused gather-aggregate (fp16 loads, fp32 accum) + TF32 tensor GEMM.
//       M-tile 64, smem 103KB -> 2 CTAs/SM so gather (L2) overlaps MMA (tensor).

#define MAX_NODES 100000
#define D 128

__device__ __half g_xh[(size_t)MAX_NODES * D];  // 25.6 MB fp16 scratch

#define SA 132  // A tile row stride (floats): 128 + 4 pad
#define SB 136  // B tile row stride (floats): 128 + 8 pad

__device__ __forceinline__ float f2tf32(float x) {
    unsigned y;
    asm("cvt.rna.tf32.f32 %0, %1;" : "=r"(y) : "f"(x));
    return __uint_as_float(y);
}

__device__ __forceinline__ void mma_tf32(float c[4], const unsigned a[4],
                                         const unsigned b[2]) {
    asm volatile(
        "mma.sync.aligned.m16n8k8.row.col.f32.tf32.tf32.f32 "
        "{%0,%1,%2,%3}, {%4,%5,%6,%7}, {%8,%9}, {%0,%1,%2,%3};"
        : "+f"(c[0]), "+f"(c[1]), "+f"(c[2]), "+f"(c[3])
        : "r"(a[0]), "r"(a[1]), "r"(a[2]), "r"(a[3]), "r"(b[0]), "r"(b[1]));
}

// ---------------------------------------------------------------------------
// K1: X fp32 -> fp16. HBM-bound one-shot pass (~77 MB).
// ---------------------------------------------------------------------------
__global__ void convert_kernel(const float* __restrict__ X, int n4) {
    int idx = blockIdx.x * blockDim.x + threadIdx.x;
    if (idx >= n4) return;
    float4 v = ((const float4*)X)[idx];
    __half2 h0 = __floats2half2_rn(v.x, v.y);
    __half2 h1 = __floats2half2_rn(v.z, v.w);
    uint2 u;
    u.x = *(unsigned*)&h0;
    u.y = *(unsigned*)&h1;
    ((uint2*)g_xh)[idx] = u;
}

// ---------------------------------------------------------------------------
// K2: fused gather + GEMM.
// CTA: 256 threads (8 warps), M-tile = 64 rows, full N=128, full K=128.
//   Phase 1: load W -> Bs (tf32). Each warp gathers 8 nodes: per edge, the
//            warp reads one 256B fp16 row (lane = 4 halves), fp32-accumulates,
//            stores tf32 row to As.
//   Phase 2: warps in 2(M) x 4(N); warp tile 32x32 via m16n8k8 tf32 mma.
// Bank analysis (conflict-free):
//   A frag:  idx%32 = (4g + t + c) -> unique per lane (SA=132)
//   B frag:  idx%32 = (8t + g + c) -> unique per lane (SB=136)
// ---------------------------------------------------------------------------
__global__ void __launch_bounds__(256, 2)
fused_kernel(const float* __restrict__ W,
             const int* __restrict__ rowptr,
             const int* __restrict__ colidx,
             float* __restrict__ out, int n_nodes) {
    extern __shared__ float smem[];
    float* As = smem;            // [64][SA]
    float* Bs = smem + 64 * SA;  // [128][SB]

    const int tid = threadIdx.x;
    const int lane = tid & 31;
    const int warp = tid >> 5;
    const int g = lane >> 2;  // 0..7
    const int t = lane & 3;   // 0..3

    const int block_row = blockIdx.x * 64;

    // --- load W -> Bs (tf32-rounded) ---
    #pragma unroll
    for (int i = 0; i < 16; i++) {
        int idx = i * 256 + tid;  // float4 index over 128x128
        int k = idx >> 5;
        int n4 = idx & 31;
        float4 v = ((const float4*)W)[idx];
        float4 w = make_float4(f2tf32(v.x), f2tf32(v.y), f2tf32(v.z), f2tf32(v.w));
        *(float4*)(Bs + k * SB + n4 * 4) = w;
    }

    // --- gather-aggregate 8 nodes per warp into As ---
    const __half* __restrict__ Xh = g_xh;
    #pragma unroll
    for (int j = 0; j < 8; j++) {
        int r = warp * 8 + j;       // local row 0..63
        int gn = block_row + r;     // global node
        float4 acc = make_float4(0.f, 0.f, 0.f, 0.f);
        if (gn < n_nodes) {
            int s = rowptr[gn];
            int e = rowptr[gn + 1];
            int i = s;
            for (; i + 4 <= e; i += 4) {
                int c0 = colidx[i + 0];
                int c1 = colidx[i + 1];
                int c2 = colidx[i + 2];
                int c3 = colidx[i + 3];
                uint2 u0 = ((const uint2*)(Xh + (size_t)c0 * D))[lane];
                uint2 u1 = ((const uint2*)(Xh + (size_t)c1 * D))[lane];
                uint2 u2 = ((const uint2*)(Xh + (size_t)c2 * D))[lane];
                uint2 u3 = ((const uint2*)(Xh + (size_t)c3 * D))[lane];
                float2 a0 = __half22float2(*(__half2*)&u0.x);
                float2 b0 = __half22float2(*(__half2*)&u0.y);
                float2 a1 = __half22float2(*(__half2*)&u1.x);
                float2 b1 = __half22float2(*(__half2*)&u1.y);
                float2 a2 = __half22float2(*(__half2*)&u2.x);
                float2 b2 = __half22float2(*(__half2*)&u2.y);
                float2 a3 = __half22float2(*(__half2*)&u3.x);
                float2 b3 = __half22float2(*(__half2*)&u3.y);
                acc.x += (a0.x + a1.x) + (a2.x + a3.x);
                acc.y += (a0.y + a1.y) + (a2.y + a3.y);
                acc.z += (b0.x + b1.x) + (b2.x + b3.x);
                acc.w += (b0.y + b1.y) + (b2.y + b3.y);
            }
            for (; i < e; i++) {
                int c = colidx[i];
                uint2 u = ((const uint2*)(Xh + (size_t)c * D))[lane];
                float2 a = __half22float2(*(__half2*)&u.x);
                float2 b = __half22float2(*(__half2*)&u.y);
                acc.x += a.x; acc.y += a.y; acc.z += b.x; acc.w += b.y;
            }
        }
        float4 w = make_float4(f2tf32(acc.x), f2tf32(acc.y),
                               f2tf32(acc.z), f2tf32(acc.w));
        *(float4*)(As + r * SA + lane * 4) = w;
    }
    __syncthreads();

    // --- MMA mainloop: warp tile 32(M) x 32(N) ---
    const int warp_row = (warp & 1) * 32;   // 0,32
    const int warp_col = (warp >> 1) * 32;  // 0,32,64,96

    float c[2][4][4];
    #pragma unroll
    for (int mi = 0; mi < 2; mi++)
        #pragma unroll
        for (int ni = 0; ni < 4; ni++)
            #pragma unroll
            for (int q = 0; q < 4; q++) c[mi][ni][q] = 0.f;

    #pragma unroll
    for (int k0 = 0; k0 < 128; k0 += 8) {
        unsigned a[2][4];
        #pragma unroll
        for (int mi = 0; mi < 2; mi++) {
            int r0 = warp_row + mi * 16 + g;
            a[mi][0] = __float_as_uint(As[r0 * SA + k0 + t]);
            a[mi][1] = __float_as_uint(As[(r0 + 8) * SA + k0 + t]);
            a[mi][2] = __float_as_uint(As[r0 * SA + k0 + t + 4]);
            a[mi][3] = __float_as_uint(As[(r0 + 8) * SA + k0 + t + 4]);
        }
        unsigned b[4][2];
        #pragma unroll
        for (int ni = 0; ni < 4; ni++) {
            int cn = warp_col + ni * 8 + g;
            b[ni][0] = __float_as_uint(Bs[(k0 + t) * SB + cn]);
            b[ni][1] = __float_as_uint(Bs[(k0 + t + 4) * SB + cn]);
        }
        #pragma unroll
        for (int mi = 0; mi < 2; mi++)
            #pragma unroll
            for (int ni = 0; ni < 4; ni++)
                mma_tf32(c[mi][ni], a[mi], b[ni]);
    }

    // --- epilogue ---
    #pragma unroll
    for (int mi = 0; mi < 2; mi++) {
        int r_lo = block_row + warp_row + mi * 16 + g;
        int r_hi = r_lo + 8;
        #pragma unroll
        for (int ni = 0; ni < 4; ni++) {
            int col = warp_col + ni * 8 + 2 * t;
            if (r_lo < n_nodes)
                *(float2*)(out + (size_t)r_lo * 128 + col) =
                    make_float2(c[mi][ni][0], c[mi][ni][1]);
            if (r_hi < n_nodes)
                *(float2*)(out + (size_t)r_hi * 128 + col) =
                    make_float2(c[mi][ni][2], c[mi][ni][3]);
        }
    }
}

// ---------------------------------------------------------------------------
extern "C" void kernel_launch(void* const* d_in, const int* in_sizes, int n_in,
                              void* d_out, int out_size) {
    const float* X      = (const float*)d_in[0];
    const float* W      = (const float*)d_in[1];
    const int*   rowptr = (const int*)d_in[2];
    const int*   colidx = (const int*)d_in[3];
    float*       out    = (float*)d_out;

    int n_nodes = in_sizes[2] - 1;
    if (n_nodes > MAX_NODES) n_nodes = MAX_NODES;

    // K1: fp32 -> fp16 (vectorized by 4)
    int n4 = n_nodes * (D / 4);
    convert_kernel<<<(n4 + 255) / 256, 256>>>(X, n4);

    // K2: fused gather + GEMM
    static const size_t smem_bytes = (size_t)(64 * SA + 128 * SB) * sizeof(float);
    cudaFuncSetAttribute(fused_kernel,
                         cudaFuncAttributeMaxDynamicSharedMemorySize,
                         (int)smem_bytes);
    int blocks = (n_nodes + 63) / 64;
    fused_kernel<<<blocks, 256, smem_bytes>>>(W, rowptr, colidx, out, n_nodes);
}

// round 4
// speedup vs baseline: 2.0433x; 2.0433x over previous
#include <cuda_runtime.h>
#include <cuda_fp16.h>
#include <cstdint>

// GINConv: out = SegmentSum_CSR(X[col]) @ W  ==  SegmentSum_CSR((X@W)[col])
// (N=100000, DEG=16, D=128). Reordered by linearity:
//   K0: transpose+convert W -> g_wt fp16 [n][k]            (tiny)
//   K1: GEMM Y = X @ W, fp16 m16n8k16 MMA, epilogue stores Y as fp16
//   K2: gather-aggregate Y_h rows (warp-per-node, 100k warps, MLP=8),
//       fp32 accumulate, write fp32 output.

#define MAX_NODES 100000
#define D 128

__device__ __half g_y[(size_t)MAX_NODES * D];  // 25.6 MB Y=X@W scratch (fp16)
__device__ __half g_wt[D * D];                 // W^T fp16 [n][k]

// smem row stride: 136 halves = 68 uint32; 68 mod 32 = 4 -> fragment loads
// hit banks (4g+t) mod 32, unique per lane. Conflict-free.
#define SROW32 68

__device__ __forceinline__ void mma_f16(float c[4], const unsigned a[4],
                                        const unsigned b[2]) {
    asm volatile(
        "mma.sync.aligned.m16n8k16.row.col.f32.f16.f16.f32 "
        "{%0,%1,%2,%3}, {%4,%5,%6,%7}, {%8,%9}, {%0,%1,%2,%3};"
        : "+f"(c[0]), "+f"(c[1]), "+f"(c[2]), "+f"(c[3])
        : "r"(a[0]), "r"(a[1]), "r"(a[2]), "r"(a[3]), "r"(b[0]), "r"(b[1]));
}

// ---------------------------------------------------------------------------
// K0: W [k][n] fp32 -> g_wt [n][k] fp16 (16K elements, trivial)
// ---------------------------------------------------------------------------
__global__ void wt_kernel(const float* __restrict__ W) {
    int idx = blockIdx.x * blockDim.x + threadIdx.x;  // [0, 16384)
    if (idx >= D * D) return;
    int k = idx >> 7;
    int n = idx & 127;
    g_wt[n * D + k] = __float2half_rn(W[idx]);
}

// ---------------------------------------------------------------------------
// K1: Y = X @ W, fp16 tensor cores. CTA 256 threads, tile 128(M) x 128(N),
// K=128 one-shot. Warps 4(M) x 2(N) -> warp tile 32x64.
// A filled from X fp32 (converted to fp16 in the fill), B from g_wt.
// Epilogue: fp32 accum -> fp16 -> g_y.
// ---------------------------------------------------------------------------
__global__ void __launch_bounds__(256, 2)
gemm_kernel(const float* __restrict__ X, int n_nodes) {
    extern __shared__ unsigned smem32[];
    unsigned* As = smem32;                 // [128][SROW32] as uint32 (2 halves)
    unsigned* Bs = smem32 + 128 * SROW32;  // [128][SROW32]

    const int tid = threadIdx.x;
    const int lane = tid & 31;
    const int warp = tid >> 5;
    const int g = lane >> 2;  // 0..7
    const int t = lane & 3;   // 0..3

    const int block_row = blockIdx.x * 128;

    // --- fill As: X rows (fp32 -> fp16), 128 rows x 32 float4 ---
    #pragma unroll
    for (int i = 0; i < 16; i++) {
        int idx = i * 256 + tid;
        int r = idx >> 5;
        int c4 = idx & 31;         // float4 col
        int gr = block_row + r;
        float4 v = make_float4(0.f, 0.f, 0.f, 0.f);
        if (gr < n_nodes) v = ((const float4*)X)[(size_t)gr * 32 + c4];
        __half2 h0 = __floats2half2_rn(v.x, v.y);
        __half2 h1 = __floats2half2_rn(v.z, v.w);
        uint2 u;
        u.x = *(unsigned*)&h0;
        u.y = *(unsigned*)&h1;
        *(uint2*)(As + r * SROW32 + c4 * 2) = u;
    }
    // --- fill Bs: g_wt rows [n][k] fp16, 128 rows x 32 uint2 (FULL k range) ---
    #pragma unroll
    for (int i = 0; i < 16; i++) {
        int idx = i * 256 + tid;   // uint2 index over 128 rows x 32
        int n = idx >> 5;
        int kq = idx & 31;         // uint2 col (4 halves) -> k in [0,128)
        uint2 u = ((const uint2*)g_wt)[n * 32 + kq];
        *(uint2*)(Bs + n * SROW32 + kq * 2) = u;
    }
    __syncthreads();

    const int warp_row = (warp & 3) * 32;   // 0,32,64,96
    const int warp_col = (warp >> 2) * 64;  // 0,64

    float c[2][8][4];
    #pragma unroll
    for (int mi = 0; mi < 2; mi++)
        #pragma unroll
        for (int ni = 0; ni < 8; ni++)
            #pragma unroll
            for (int q = 0; q < 4; q++) c[mi][ni][q] = 0.f;

    #pragma unroll
    for (int ks = 0; ks < 8; ks++) {
        const int kp = ks * 8;  // uint32 (half-pair) offset; k=16 per step
        unsigned a[2][4];
        #pragma unroll
        for (int mi = 0; mi < 2; mi++) {
            int r0 = warp_row + mi * 16 + g;
            a[mi][0] = As[r0 * SROW32 + kp + t];
            a[mi][1] = As[(r0 + 8) * SROW32 + kp + t];
            a[mi][2] = As[r0 * SROW32 + kp + t + 4];
            a[mi][3] = As[(r0 + 8) * SROW32 + kp + t + 4];
        }
        unsigned b[8][2];
        #pragma unroll
        for (int ni = 0; ni < 8; ni++) {
            int cn = warp_col + ni * 8 + g;
            b[ni][0] = Bs[cn * SROW32 + kp + t];
            b[ni][1] = Bs[cn * SROW32 + kp + t + 4];
        }
        #pragma unroll
        for (int mi = 0; mi < 2; mi++)
            #pragma unroll
            for (int ni = 0; ni < 8; ni++)
                mma_f16(c[mi][ni], a[mi], b[ni]);
    }

    // --- epilogue: accum -> fp16 -> g_y ---
    #pragma unroll
    for (int mi = 0; mi < 2; mi++) {
        int r_lo = block_row + warp_row + mi * 16 + g;
        int r_hi = r_lo + 8;
        #pragma unroll
        for (int ni = 0; ni < 8; ni++) {
            int col = warp_col + ni * 8 + 2 * t;
            if (r_lo < n_nodes) {
                __half2 h = __floats2half2_rn(c[mi][ni][0], c[mi][ni][1]);
                *(__half2*)(g_y + (size_t)r_lo * D + col) = h;
            }
            if (r_hi < n_nodes) {
                __half2 h = __floats2half2_rn(c[mi][ni][2], c[mi][ni][3]);
                *(__half2*)(g_y + (size_t)r_hi * D + col) = h;
            }
        }
    }
}

// ---------------------------------------------------------------------------
// K2: aggregation over Y (fp16). One warp per node; lane owns 4 halves (8B),
// warp reads one 256B row per edge. 8-wide edge batching for MLP.
// fp32 accumulate, fp32 output.
// ---------------------------------------------------------------------------
__global__ void agg_kernel(const int* __restrict__ rowptr,
                           const int* __restrict__ colidx,
                           float* __restrict__ out, int n_nodes) {
    int node = (int)((blockIdx.x * (unsigned)blockDim.x + threadIdx.x) >> 5);
    int lane = threadIdx.x & 31;
    if (node >= n_nodes) return;

    int s = rowptr[node];
    int e = rowptr[node + 1];

    const __half* __restrict__ Y = g_y;
    float4 acc = make_float4(0.f, 0.f, 0.f, 0.f);

    int i = s;
    for (; i + 8 <= e; i += 8) {
        uint2 u[8];
        #pragma unroll
        for (int j = 0; j < 8; j++) {
            int c = colidx[i + j];
            u[j] = ((const uint2*)(Y + (size_t)c * D))[lane];
        }
        #pragma unroll
        for (int j = 0; j < 8; j++) {
            float2 a = __half22float2(*(__half2*)&u[j].x);
            float2 b = __half22float2(*(__half2*)&u[j].y);
            acc.x += a.x; acc.y += a.y; acc.z += b.x; acc.w += b.y;
        }
    }
    for (; i < e; i++) {
        int c = colidx[i];
        uint2 u = ((const uint2*)(Y + (size_t)c * D))[lane];
        float2 a = __half22float2(*(__half2*)&u.x);
        float2 b = __half22float2(*(__half2*)&u.y);
        acc.x += a.x; acc.y += a.y; acc.z += b.x; acc.w += b.y;
    }

    ((float4*)out)[(size_t)node * 32 + lane] = acc;
}

// ---------------------------------------------------------------------------
extern "C" void kernel_launch(void* const* d_in, const int* in_sizes, int n_in,
                              void* d_out, int out_size) {
    const float* X      = (const float*)d_in[0];
    const float* W      = (const float*)d_in[1];
    const int*   rowptr = (const int*)d_in[2];
    const int*   colidx = (const int*)d_in[3];
    float*       out    = (float*)d_out;

    int n_nodes = in_sizes[2] - 1;
    if (n_nodes > MAX_NODES) n_nodes = MAX_NODES;

    // K0: W transpose + fp16
    wt_kernel<<<(D * D + 255) / 256, 256>>>(W);

    // K1: Y = X @ W (fp16 tensor cores)
    static const size_t smem_bytes = (size_t)(2 * 128 * SROW32) * sizeof(unsigned);
    cudaFuncSetAttribute(gemm_kernel,
                         cudaFuncAttributeMaxDynamicSharedMemorySize,
                         (int)smem_bytes);
    int gemm_blocks = (n_nodes + 127) / 128;
    gemm_kernel<<<gemm_blocks, 256, smem_bytes>>>(X, n_nodes);

    // K2: out[r] = sum_e Y[col(e)]  (warp per node)
    int agg_blocks = (n_nodes + 7) / 8;
    agg_kernel<<<agg_blocks, 256>>>(rowptr, colidx, out, n_nodes);
}

// round 5
// speedup vs baseline: 2.0869x; 1.0213x over previous
#include <cuda_runtime.h>
#include <cuda_fp16.h>
#include <cstdint>

// GINConv: out = SegmentSum_CSR(X[col]) @ W  ==  SegmentSum_CSR((X@W)[col])
// (N=100000, DEG=16, D=128). Two kernels:
//   K1: GEMM Y = X @ W (fp16 m16n8k16, ldmatrix), Y stored fp16 -> g_y
//       (W transposition eliminated: B kept [k][n] row-major in smem,
//        fragments loaded with ldmatrix.x4.trans)
//   K2: gather-aggregate Y rows (warp-per-node, MLP=8), fp32 accum + out.

#define MAX_NODES 100000
#define D 128

__device__ __half g_y[(size_t)MAX_NODES * D];  // 25.6 MB Y=X@W scratch (fp16)

// smem row stride: 136 halves = 68 words; 68 mod 32 = 4 -> ldmatrix rows hit
// banks 4r..4r+3, disjoint over 8 rows per phase. Conflict-free.
#define SROW32 68

__device__ __forceinline__ void mma_f16(float c[4], const unsigned a[4],
                                        const unsigned b[2]) {
    asm volatile(
        "mma.sync.aligned.m16n8k16.row.col.f32.f16.f16.f32 "
        "{%0,%1,%2,%3}, {%4,%5,%6,%7}, {%8,%9}, {%0,%1,%2,%3};"
        : "+f"(c[0]), "+f"(c[1]), "+f"(c[2]), "+f"(c[3])
        : "r"(a[0]), "r"(a[1]), "r"(a[2]), "r"(a[3]), "r"(b[0]), "r"(b[1]));
}

__device__ __forceinline__ void ldm_x4(unsigned& r0, unsigned& r1,
                                       unsigned& r2, unsigned& r3,
                                       uint32_t addr) {
    asm volatile(
        "ldmatrix.sync.aligned.m8n8.x4.shared.b16 {%0,%1,%2,%3}, [%4];"
        : "=r"(r0), "=r"(r1), "=r"(r2), "=r"(r3) : "r"(addr));
}

__device__ __forceinline__ void ldm_x4_trans(unsigned& r0, unsigned& r1,
                                             unsigned& r2, unsigned& r3,
                                             uint32_t addr) {
    asm volatile(
        "ldmatrix.sync.aligned.m8n8.x4.trans.shared.b16 {%0,%1,%2,%3}, [%4];"
        : "=r"(r0), "=r"(r1), "=r"(r2), "=r"(r3) : "r"(addr));
}

// ---------------------------------------------------------------------------
// K1: Y = X @ W. CTA 256 threads, tile 128(M) x 128(N), K=128 one-shot.
// Warps 4(M) x 2(N) -> warp tile 32x64.
//   As: [128 m][128 k] fp16 (from X fp32, converted in fill)
//   Bs: [128 k][128 n] fp16 (from W fp32, converted in fill, NO transpose)
// A frags: ldmatrix.x4; B frags: ldmatrix.x4.trans (2 n-blocks per ld).
// ---------------------------------------------------------------------------
__global__ void __launch_bounds__(256, 2)
gemm_kernel(const float* __restrict__ X, const float* __restrict__ W,
            int n_nodes) {
    extern __shared__ unsigned smem32[];
    unsigned* As = smem32;                 // [128][SROW32]
    unsigned* Bs = smem32 + 128 * SROW32;  // [128][SROW32]

    const int tid = threadIdx.x;
    const int lane = tid & 31;
    const int warp = tid >> 5;
    const int g = lane >> 2;  // 0..7
    const int t = lane & 3;   // 0..3

    const int block_row = blockIdx.x * 128;

    // --- fill As: X rows fp32 -> fp16, [m][k] ---
    #pragma unroll
    for (int i = 0; i < 16; i++) {
        int idx = i * 256 + tid;   // float4 index over 128 rows x 32
        int r = idx >> 5;
        int c4 = idx & 31;
        int gr = block_row + r;
        float4 v = make_float4(0.f, 0.f, 0.f, 0.f);
        if (gr < n_nodes) v = ((const float4*)X)[(size_t)gr * 32 + c4];
        __half2 h0 = __floats2half2_rn(v.x, v.y);
        __half2 h1 = __floats2half2_rn(v.z, v.w);
        uint2 u;
        u.x = *(unsigned*)&h0;
        u.y = *(unsigned*)&h1;
        *(uint2*)(As + r * SROW32 + c4 * 2) = u;
    }
    // --- fill Bs: W rows fp32 -> fp16, [k][n] (straight copy, no transpose) ---
    #pragma unroll
    for (int i = 0; i < 16; i++) {
        int idx = i * 256 + tid;
        int k = idx >> 5;
        int c4 = idx & 31;
        float4 v = ((const float4*)W)[idx];
        __half2 h0 = __floats2half2_rn(v.x, v.y);
        __half2 h1 = __floats2half2_rn(v.z, v.w);
        uint2 u;
        u.x = *(unsigned*)&h0;
        u.y = *(unsigned*)&h1;
        *(uint2*)(Bs + k * SROW32 + c4 * 2) = u;
    }
    __syncthreads();

    const int warp_row = (warp & 3) * 32;   // 0,32,64,96
    const int warp_col = (warp >> 2) * 64;  // 0,64

    // ldmatrix lane decomposition
    const int grp = lane >> 3;       // 0..3
    const int r8 = lane & 7;         // 0..7
    const int gL = grp & 1;          // k/m low-high selector within 16
    const int gH = grp >> 1;

    const uint32_t as_base = (uint32_t)__cvta_generic_to_shared(As);
    const uint32_t bs_base = (uint32_t)__cvta_generic_to_shared(Bs);

    // A: matrices (m-lo/k-lo, m-hi/k-lo, m-lo/k-hi, m-hi/k-hi)
    // addr = row (warp_row + mi*16 + gL*8 + r8), col halves (ks*16 + gH*8)
    const uint32_t a_addr0 =
        as_base + ((warp_row + gL * 8 + r8) * SROW32 + gH * 4) * 4;
    // B: matrices (k-lo/n-lo, k-hi/n-lo, k-lo/n-hi, k-hi/n-hi)
    // addr = row k (ks*16 + gL*8 + r8), col halves (warp_col + nj*16 + gH*8)
    const uint32_t b_addr0 =
        bs_base + ((gL * 8 + r8) * SROW32) * 4 + (warp_col + gH * 8) * 2;

    float c[2][8][4];
    #pragma unroll
    for (int mi = 0; mi < 2; mi++)
        #pragma unroll
        for (int ni = 0; ni < 8; ni++)
            #pragma unroll
            for (int q = 0; q < 4; q++) c[mi][ni][q] = 0.f;

    #pragma unroll
    for (int ks = 0; ks < 8; ks++) {
        unsigned a[2][4];
        #pragma unroll
        for (int mi = 0; mi < 2; mi++) {
            uint32_t addr = a_addr0 + mi * (16 * SROW32 * 4) + ks * 32;
            ldm_x4(a[mi][0], a[mi][1], a[mi][2], a[mi][3], addr);
        }
        unsigned b[8][2];
        #pragma unroll
        for (int nj = 0; nj < 4; nj++) {
            uint32_t addr = b_addr0 + ks * (16 * SROW32 * 4) + nj * 32;
            ldm_x4_trans(b[2 * nj][0], b[2 * nj][1],
                         b[2 * nj + 1][0], b[2 * nj + 1][1], addr);
        }
        #pragma unroll
        for (int mi = 0; mi < 2; mi++)
            #pragma unroll
            for (int ni = 0; ni < 8; ni++)
                mma_f16(c[mi][ni], a[mi], b[ni]);
    }

    // --- epilogue: fp32 accum -> fp16 -> g_y ---
    #pragma unroll
    for (int mi = 0; mi < 2; mi++) {
        int r_lo = block_row + warp_row + mi * 16 + g;
        int r_hi = r_lo + 8;
        #pragma unroll
        for (int ni = 0; ni < 8; ni++) {
            int col = warp_col + ni * 8 + 2 * t;
            if (r_lo < n_nodes) {
                __half2 h = __floats2half2_rn(c[mi][ni][0], c[mi][ni][1]);
                *(__half2*)(g_y + (size_t)r_lo * D + col) = h;
            }
            if (r_hi < n_nodes) {
                __half2 h = __floats2half2_rn(c[mi][ni][2], c[mi][ni][3]);
                *(__half2*)(g_y + (size_t)r_hi * D + col) = h;
            }
        }
    }
}

// ---------------------------------------------------------------------------
// K2: aggregation over Y (fp16). One warp per node; lane owns 4 halves (8B),
// warp reads one 256B row per edge. 8-wide edge batching for MLP.
// ---------------------------------------------------------------------------
__global__ void agg_kernel(const int* __restrict__ rowptr,
                           const int* __restrict__ colidx,
                           float* __restrict__ out, int n_nodes) {
    int node = (int)((blockIdx.x * (unsigned)blockDim.x + threadIdx.x) >> 5);
    int lane = threadIdx.x & 31;
    if (node >= n_nodes) return;

    int s = rowptr[node];
    int e = rowptr[node + 1];

    const __half* __restrict__ Y = g_y;
    float4 acc = make_float4(0.f, 0.f, 0.f, 0.f);

    int i = s;
    for (; i + 8 <= e; i += 8) {
        uint2 u[8];
        #pragma unroll
        for (int j = 0; j < 8; j++) {
            int c = colidx[i + j];
            u[j] = ((const uint2*)(Y + (size_t)c * D))[lane];
        }
        #pragma unroll
        for (int j = 0; j < 8; j++) {
            float2 a = __half22float2(*(__half2*)&u[j].x);
            float2 b = __half22float2(*(__half2*)&u[j].y);
            acc.x += a.x; acc.y += a.y; acc.z += b.x; acc.w += b.y;
        }
    }
    for (; i < e; i++) {
        int c = colidx[i];
        uint2 u = ((const uint2*)(Y + (size_t)c * D))[lane];
        float2 a = __half22float2(*(__half2*)&u.x);
        float2 b = __half22float2(*(__half2*)&u.y);
        acc.x += a.x; acc.y += a.y; acc.z += b.x; acc.w += b.y;
    }

    ((float4*)out)[(size_t)node * 32 + lane] = acc;
}

// ---------------------------------------------------------------------------
extern "C" void kernel_launch(void* const* d_in, const int* in_sizes, int n_in,
                              void* d_out, int out_size) {
    const float* X      = (const float*)d_in[0];
    const float* W      = (const float*)d_in[1];
    const int*   rowptr = (const int*)d_in[2];
    const int*   colidx = (const int*)d_in[3];
    float*       out    = (float*)d_out;

    int n_nodes = in_sizes[2] - 1;
    if (n_nodes > MAX_NODES) n_nodes = MAX_NODES;

    // K1: Y = X @ W (fp16 tensor cores, W consumed directly)
    static const size_t smem_bytes = (size_t)(2 * 128 * SROW32) * sizeof(unsigned);
    cudaFuncSetAttribute(gemm_kernel,
                         cudaFuncAttributeMaxDynamicSharedMemorySize,
                         (int)smem_bytes);
    int gemm_blocks = (n_nodes + 127) / 128;
    gemm_kernel<<<gemm_blocks, 256, smem_bytes>>>(X, W, n_nodes);

    // K2: out[r] = sum_e Y[col(e)]  (warp per node)
    int agg_blocks = (n_nodes + 7) / 8;
    agg_kernel<<<agg_blocks, 256>>>(rowptr, colidx, out, n_nodes);
}